// round 2
// baseline (speedup 1.0000x reference)
#include <cuda_runtime.h>
#include <cstdint>

// Scratch (device globals; no allocations allowed)
__device__ float g_h1[(size_t)16 * 32 * 2048];
__device__ float g_bufA[(size_t)16 * 64 * 1024];
__device__ float g_bufB[(size_t)16 * 64 * 1024];
__device__ float g_t1[(size_t)16 * 32 * 2048];

// ---------------------------------------------------------------------------
// conv1: 768 -> 32, K=4, S=2, P=1, bias, ReLU.  Tile: 64 out positions.
// grid (32,16). smem: xs[32][130] + ws[32][4][32]. x via float2 (conflict-free)
// ---------------------------------------------------------------------------
__global__ void __launch_bounds__(256) k_conv1(
    const float* __restrict__ x, const float* __restrict__ w,
    const float* __restrict__ bias, float* __restrict__ out)
{
    extern __shared__ float sm[];
    float* xs = sm;               // [32][130]
    float* ws = sm + 32 * 130;    // [32][4][32]
    const int n   = blockIdx.y;
    const int t0  = blockIdx.x * 64;
    const int tid = threadIdx.x;
    const int lane = tid & 31;
    const int ocg  = tid >> 5;    // 8 groups x 4 oc
    const int xbase = 2 * t0 - 1;

    float acc[4][2];
#pragma unroll
    for (int r = 0; r < 4; r++)
#pragma unroll
        for (int i = 0; i < 2; i++) acc[r][i] = 0.f;

    for (int c0 = 0; c0 < 768; c0 += 32) {
        __syncthreads();
        for (int idx = tid; idx < 32 * 130; idx += 256) {
            int c = idx / 130, j = idx - c * 130;
            int g = xbase + j;
            float v = 0.f;
            if (g >= 0 && g < 4096) v = x[((size_t)(n * 768 + c0 + c)) * 4096 + g];
            xs[idx] = v;
        }
        for (int idx = tid; idx < 32 * 4 * 32; idx += 256) {
            int c = idx >> 7, rem = idx & 127, k = rem >> 5, o = rem & 31;
            ws[idx] = w[((size_t)o * 768 + c0 + c) * 4 + k];
        }
        __syncthreads();
#pragma unroll 4
        for (int c = 0; c < 32; c++) {
            const float2* xr2 = (const float2*)(xs + c * 130);
            const float4* wr  = (const float4*)(ws + c * 128);
            float4 w0 = wr[ocg], w1 = wr[8 + ocg], w2 = wr[16 + ocg], w3 = wr[24 + ocg];
#pragma unroll
            for (int i = 0; i < 2; i++) {
                float2 pa = xr2[lane + 32 * i];
                float2 pb = xr2[lane + 32 * i + 1];
                acc[0][i] = fmaf(w0.x, pa.x, acc[0][i]);
                acc[1][i] = fmaf(w0.y, pa.x, acc[1][i]);
                acc[2][i] = fmaf(w0.z, pa.x, acc[2][i]);
                acc[3][i] = fmaf(w0.w, pa.x, acc[3][i]);
                acc[0][i] = fmaf(w1.x, pa.y, acc[0][i]);
                acc[1][i] = fmaf(w1.y, pa.y, acc[1][i]);
                acc[2][i] = fmaf(w1.z, pa.y, acc[2][i]);
                acc[3][i] = fmaf(w1.w, pa.y, acc[3][i]);
                acc[0][i] = fmaf(w2.x, pb.x, acc[0][i]);
                acc[1][i] = fmaf(w2.y, pb.x, acc[1][i]);
                acc[2][i] = fmaf(w2.z, pb.x, acc[2][i]);
                acc[3][i] = fmaf(w2.w, pb.x, acc[3][i]);
                acc[0][i] = fmaf(w3.x, pb.y, acc[0][i]);
                acc[1][i] = fmaf(w3.y, pb.y, acc[1][i]);
                acc[2][i] = fmaf(w3.z, pb.y, acc[2][i]);
                acc[3][i] = fmaf(w3.w, pb.y, acc[3][i]);
            }
        }
    }
#pragma unroll
    for (int r = 0; r < 4; r++) {
        int oc = ocg * 4 + r;
        float bv = bias[oc];
#pragma unroll
        for (int i = 0; i < 2; i++)
            out[((size_t)(n * 32 + oc)) * 2048 + t0 + lane + 32 * i] =
                fmaxf(acc[r][i] + bv, 0.f);
    }
}

// ---------------------------------------------------------------------------
// conv2: 32 -> 64, K=4, S=2, P=1, bias, ReLU. Tile 64. grid (16,16)
// ---------------------------------------------------------------------------
__global__ void __launch_bounds__(256) k_conv2(
    const float* __restrict__ x, const float* __restrict__ w,
    const float* __restrict__ bias, float* __restrict__ out)
{
    extern __shared__ float sm[];
    float* xs = sm;             // [32][130]
    float* ws = sm + 32 * 130;  // [32][4][64]
    const int n = blockIdx.y;
    const int t0 = blockIdx.x * 64;
    const int tid = threadIdx.x, lane = tid & 31, ocg = tid >> 5;
    const int xbase = 2 * t0 - 1;

    for (int idx = tid; idx < 32 * 130; idx += 256) {
        int c = idx / 130, j = idx - c * 130;
        int g = xbase + j;
        float v = 0.f;
        if (g >= 0 && g < 2048) v = x[((size_t)(n * 32 + c)) * 2048 + g];
        xs[idx] = v;
    }
    for (int idx = tid; idx < 32 * 4 * 64; idx += 256) {
        int c = idx >> 8, rem = idx & 255, k = rem >> 6, o = rem & 63;
        ws[idx] = w[((size_t)o * 32 + c) * 4 + k];
    }
    __syncthreads();

    float acc[8][2];
#pragma unroll
    for (int r = 0; r < 8; r++)
#pragma unroll
        for (int i = 0; i < 2; i++) acc[r][i] = 0.f;

#pragma unroll 4
    for (int c = 0; c < 32; c++) {
        const float2* xr2 = (const float2*)(xs + c * 130);
        const float4* wr  = (const float4*)(ws + c * 256);
#pragma unroll
        for (int k = 0; k < 4; k++) {
            float4 w0 = wr[k * 16 + ocg * 2];
            float4 w1 = wr[k * 16 + ocg * 2 + 1];
#pragma unroll
            for (int i = 0; i < 2; i++) {
                float2 pa = xr2[lane + 32 * i + (k >> 1)];
                float xv = (k & 1) ? pa.y : pa.x;
                acc[0][i] = fmaf(w0.x, xv, acc[0][i]);
                acc[1][i] = fmaf(w0.y, xv, acc[1][i]);
                acc[2][i] = fmaf(w0.z, xv, acc[2][i]);
                acc[3][i] = fmaf(w0.w, xv, acc[3][i]);
                acc[4][i] = fmaf(w1.x, xv, acc[4][i]);
                acc[5][i] = fmaf(w1.y, xv, acc[5][i]);
                acc[6][i] = fmaf(w1.z, xv, acc[6][i]);
                acc[7][i] = fmaf(w1.w, xv, acc[7][i]);
            }
        }
    }
#pragma unroll
    for (int r = 0; r < 8; r++) {
        int oc = ocg * 8 + r;
        float bv = bias[oc];
#pragma unroll
        for (int i = 0; i < 2; i++)
            out[((size_t)(n * 64 + oc)) * 1024 + t0 + lane + 32 * i] =
                fmaxf(acc[r][i] + bv, 0.f);
    }
}

// ---------------------------------------------------------------------------
// Generic 64->64 conv, K in {1,3}. Tile 64. grid (16,16)
// ---------------------------------------------------------------------------
template <int K, bool RELU>
__global__ void __launch_bounds__(256) k_conv64(
    const float* __restrict__ x, const float* __restrict__ w,
    const float* __restrict__ bias, float* __restrict__ out)
{
    constexpr int PAD = (K - 1) / 2;
    constexpr int XR = 64 + K - 1;
    extern __shared__ float sm[];
    float* xs = sm;             // [64][XR]
    float* ws = sm + 64 * XR;   // [64][K][64]
    const int n = blockIdx.y;
    const int t0 = blockIdx.x * 64;
    const int tid = threadIdx.x, lane = tid & 31, ocg = tid >> 5;

    for (int idx = tid; idx < 64 * XR; idx += 256) {
        int c = idx / XR, j = idx - c * XR;
        int g = t0 - PAD + j;
        float v = 0.f;
        if (g >= 0 && g < 1024) v = x[((size_t)(n * 64 + c)) * 1024 + g];
        xs[idx] = v;
    }
    for (int idx = tid; idx < 64 * K * 64; idx += 256) {
        int o = idx & 63, ck = idx >> 6;
        int k = ck % K, c = ck / K;
        ws[idx] = w[((size_t)o * 64 + c) * K + k];
    }
    __syncthreads();

    float acc[8][2];
#pragma unroll
    for (int r = 0; r < 8; r++)
#pragma unroll
        for (int i = 0; i < 2; i++) acc[r][i] = 0.f;

#pragma unroll 4
    for (int c = 0; c < 64; c++) {
        const float* xr = xs + c * XR;
        const float4* wr = (const float4*)(ws + c * K * 64);
#pragma unroll
        for (int k = 0; k < K; k++) {
            float4 w0 = wr[k * 16 + ocg * 2];
            float4 w1 = wr[k * 16 + ocg * 2 + 1];
#pragma unroll
            for (int i = 0; i < 2; i++) {
                float xv = xr[lane + 32 * i + k];
                acc[0][i] = fmaf(w0.x, xv, acc[0][i]);
                acc[1][i] = fmaf(w0.y, xv, acc[1][i]);
                acc[2][i] = fmaf(w0.z, xv, acc[2][i]);
                acc[3][i] = fmaf(w0.w, xv, acc[3][i]);
                acc[4][i] = fmaf(w1.x, xv, acc[4][i]);
                acc[5][i] = fmaf(w1.y, xv, acc[5][i]);
                acc[6][i] = fmaf(w1.z, xv, acc[6][i]);
                acc[7][i] = fmaf(w1.w, xv, acc[7][i]);
            }
        }
    }
#pragma unroll
    for (int r = 0; r < 8; r++) {
        int oc = ocg * 8 + r;
        float v0 = bias[oc];
#pragma unroll
        for (int i = 0; i < 2; i++) {
            float v = acc[r][i] + v0;
            if (RELU) v = fmaxf(v, 0.f);
            out[((size_t)(n * 64 + oc)) * 1024 + t0 + lane + 32 * i] = v;
        }
    }
}

// ---------------------------------------------------------------------------
// Fused residual block, tile 64, grid (16,16)
// ---------------------------------------------------------------------------
template <bool FINAL_RELU>
__global__ void __launch_bounds__(256) k_resblock(
    const float* __restrict__ x, const float* __restrict__ w1,
    const float* __restrict__ w2, float* __restrict__ out)
{
    extern __shared__ float sm[];
    float* xs  = sm;                 // [64][66]
    float* w1s = sm + 64 * 66;       // [64][3][32]
    float* hs  = w1s + 64 * 3 * 32;  // [32][64]
    float* w2s = hs + 32 * 64;       // [32][64]
    const int n = blockIdx.y, t0 = blockIdx.x * 64;
    const int tid = threadIdx.x, lane = tid & 31, ocg = tid >> 5;

    for (int idx = tid; idx < 64 * 66; idx += 256) {
        int c = idx / 66, j = idx - c * 66;
        int g = t0 - 1 + j;
        float v = 0.f;
        if (g >= 0 && g < 1024) v = x[((size_t)(n * 64 + c)) * 1024 + g];
        xs[idx] = v;
    }
    for (int idx = tid; idx < 64 * 3 * 32; idx += 256) {
        int o = idx & 31, ck = idx >> 5;
        int k = ck % 3, c = ck / 3;
        w1s[idx] = w1[((size_t)o * 64 + c) * 3 + k];
    }
    for (int idx = tid; idx < 32 * 64; idx += 256) {
        int o = idx & 63, c = idx >> 6;
        w2s[idx] = w2[(size_t)o * 32 + c];
    }
    __syncthreads();

    // Phase 1: h = relu(conv3(relu(x)))  (32 ch)
    {
        float acc[4][2];
#pragma unroll
        for (int r = 0; r < 4; r++)
#pragma unroll
            for (int i = 0; i < 2; i++) acc[r][i] = 0.f;
#pragma unroll 4
        for (int c = 0; c < 64; c++) {
            const float* xr = xs + c * 66;
            const float4* wr = (const float4*)(w1s + c * 96);
#pragma unroll
            for (int k = 0; k < 3; k++) {
                float4 wv = wr[k * 8 + ocg];
#pragma unroll
                for (int i = 0; i < 2; i++) {
                    float xv = fmaxf(xr[lane + 32 * i + k], 0.f);
                    acc[0][i] = fmaf(wv.x, xv, acc[0][i]);
                    acc[1][i] = fmaf(wv.y, xv, acc[1][i]);
                    acc[2][i] = fmaf(wv.z, xv, acc[2][i]);
                    acc[3][i] = fmaf(wv.w, xv, acc[3][i]);
                }
            }
        }
#pragma unroll
        for (int r = 0; r < 4; r++)
#pragma unroll
            for (int i = 0; i < 2; i++)
                hs[(ocg * 4 + r) * 64 + lane + 32 * i] = fmaxf(acc[r][i], 0.f);
    }
    __syncthreads();

    // Phase 2: out = x + w2 @ h
    {
        float acc[8][2];
#pragma unroll
        for (int r = 0; r < 8; r++)
#pragma unroll
            for (int i = 0; i < 2; i++) acc[r][i] = 0.f;
#pragma unroll 8
        for (int c = 0; c < 32; c++) {
            const float* hr = hs + c * 64;
            const float4* wr = (const float4*)(w2s + c * 64);
            float4 w0 = wr[ocg * 2];
            float4 w1v = wr[ocg * 2 + 1];
#pragma unroll
            for (int i = 0; i < 2; i++) {
                float hv = hr[lane + 32 * i];
                acc[0][i] = fmaf(w0.x, hv, acc[0][i]);
                acc[1][i] = fmaf(w0.y, hv, acc[1][i]);
                acc[2][i] = fmaf(w0.z, hv, acc[2][i]);
                acc[3][i] = fmaf(w0.w, hv, acc[3][i]);
                acc[4][i] = fmaf(w1v.x, hv, acc[4][i]);
                acc[5][i] = fmaf(w1v.y, hv, acc[5][i]);
                acc[6][i] = fmaf(w1v.z, hv, acc[6][i]);
                acc[7][i] = fmaf(w1v.w, hv, acc[7][i]);
            }
        }
#pragma unroll
        for (int r = 0; r < 8; r++) {
            int oc = ocg * 8 + r;
#pragma unroll
            for (int i = 0; i < 2; i++) {
                float v = xs[oc * 66 + lane + 32 * i + 1] + acc[r][i];
                if (FINAL_RELU) v = fmaxf(v, 0.f);
                out[((size_t)(n * 64 + oc)) * 1024 + t0 + lane + 32 * i] = v;
            }
        }
    }
}

// ---------------------------------------------------------------------------
// VQ: 512 threads, 64 positions/block, 8 code-chunks of 64. grid 256.
// Codebook rows broadcast within warp (all lanes same j).
// ---------------------------------------------------------------------------
__global__ void __launch_bounds__(512) k_vq(
    const float* __restrict__ z, const float* __restrict__ emb,
    float* __restrict__ q)
{
    extern __shared__ float sm[];
    float* es = sm;                         // [512][68]
    float* ns = sm + 512 * 68;              // [512]
    unsigned long long* red = (unsigned long long*)(ns + 512); // [512]
    int* bidx = (int*)(red + 512);          // [64]
    const int tid = threadIdx.x;
    const int p = tid & 63;
    const int chunk = tid >> 6;             // 0..7

    for (int idx = tid; idx < 512 * 64; idx += 512) {
        int j = idx >> 6, c = idx & 63;
        es[j * 68 + c] = emb[idx];
    }
    __syncthreads();
    {
        const float* er = es + tid * 68;
        float s = 0.f;
#pragma unroll 8
        for (int c = 0; c < 64; c++) { float v = er[c]; s = fmaf(v, v, s); }
        ns[tid] = s;
    }
    __syncthreads();

    const int bx = blockIdx.x;
    const int n = bx >> 4;
    const int t = ((bx & 15) << 6) + p;

    float zv[64];
#pragma unroll
    for (int c = 0; c < 64; c++) zv[c] = z[((size_t)(n * 64 + c)) * 1024 + t];

    unsigned long long best = ~0ull;
    const int j0 = chunk * 64;
    for (int j = j0; j < j0 + 64; j++) {
        const float4* er = (const float4*)(es + j * 68);
        float d0 = 0.f, d1 = 0.f, d2 = 0.f, d3 = 0.f;
#pragma unroll
        for (int c4 = 0; c4 < 16; c4 += 4) {
            float4 e0 = er[c4], e1 = er[c4 + 1], e2 = er[c4 + 2], e3 = er[c4 + 3];
            d0 = fmaf(zv[4 * c4 + 0], e0.x, d0);
            d0 = fmaf(zv[4 * c4 + 1], e0.y, d0);
            d0 = fmaf(zv[4 * c4 + 2], e0.z, d0);
            d0 = fmaf(zv[4 * c4 + 3], e0.w, d0);
            d1 = fmaf(zv[4 * c4 + 4], e1.x, d1);
            d1 = fmaf(zv[4 * c4 + 5], e1.y, d1);
            d1 = fmaf(zv[4 * c4 + 6], e1.z, d1);
            d1 = fmaf(zv[4 * c4 + 7], e1.w, d1);
            d2 = fmaf(zv[4 * c4 + 8], e2.x, d2);
            d2 = fmaf(zv[4 * c4 + 9], e2.y, d2);
            d2 = fmaf(zv[4 * c4 + 10], e2.z, d2);
            d2 = fmaf(zv[4 * c4 + 11], e2.w, d2);
            d3 = fmaf(zv[4 * c4 + 12], e3.x, d3);
            d3 = fmaf(zv[4 * c4 + 13], e3.y, d3);
            d3 = fmaf(zv[4 * c4 + 14], e3.z, d3);
            d3 = fmaf(zv[4 * c4 + 15], e3.w, d3);
        }
        float dist = ns[j] - 2.f * ((d0 + d1) + (d2 + d3));
        int s = __float_as_int(dist);
        unsigned u = (unsigned)s ^ ((unsigned)(s >> 31) | 0x80000000u);
        unsigned long long key = ((unsigned long long)u << 32) | (unsigned)j;
        best = key < best ? key : best;
    }
    red[tid] = best;
    __syncthreads();
    if (tid < 64) {
        unsigned long long m = red[tid];
#pragma unroll
        for (int c = 1; c < 8; c++) {
            unsigned long long v = red[c * 64 + tid];
            m = v < m ? v : m;
        }
        bidx[tid] = (int)(m & 0xffffffffu);
    }
    __syncthreads();

    const float* row = es + bidx[p] * 68;
#pragma unroll
    for (int c8 = 0; c8 < 8; c8++) {
        int c = chunk * 8 + c8;
        q[((size_t)(n * 64 + c)) * 1024 + t] = row[c];
    }
}

// ---------------------------------------------------------------------------
// ConvTranspose1d 64->32, K=4, S=2, P=1, bias, ReLU. Tile 128 out. grid (16,16)
// ---------------------------------------------------------------------------
__global__ void __launch_bounds__(256) k_dect1(
    const float* __restrict__ x, const float* __restrict__ w,
    const float* __restrict__ bias, float* __restrict__ out)
{
    extern __shared__ float sm[];
    float* xs = sm;             // [64][66]
    float* ws = sm + 64 * 66;   // [64][4][32]
    const int n = blockIdx.y;
    const int p0 = blockIdx.x * 128;
    const int t0in = (p0 >> 1) - 1;
    const int tid = threadIdx.x, lane = tid & 31, ocg = tid >> 5;

    for (int idx = tid; idx < 64 * 66; idx += 256) {
        int c = idx / 66, j = idx - c * 66;
        int g = t0in + j;
        float v = 0.f;
        if (g >= 0 && g < 1024) v = x[((size_t)(n * 64 + c)) * 1024 + g];
        xs[idx] = v;
    }
    for (int idx = tid; idx < 64 * 4 * 32; idx += 256) {
        int o = idx & 31, ck = idx >> 5;
        int k = ck & 3, c = ck >> 2;
        ws[idx] = w[((size_t)c * 32 + o) * 4 + k];
    }
    __syncthreads();

    const int par = lane & 1;
    const int ka = 1 - par, kb = ka + 2;
    const int ja0 = ((lane + 1 - ka) >> 1) + 1;

    float acc[4][4];
#pragma unroll
    for (int r = 0; r < 4; r++)
#pragma unroll
        for (int i = 0; i < 4; i++) acc[r][i] = 0.f;

#pragma unroll 4
    for (int c = 0; c < 64; c++) {
        const float* xr = xs + c * 66;
        const float4* wr = (const float4*)(ws + c * 128);
        float4 wa = wr[ka * 8 + ocg];
        float4 wb = wr[kb * 8 + ocg];
#pragma unroll
        for (int i = 0; i < 4; i++) {
            float xa = xr[ja0 + 16 * i];
            float xb = xr[ja0 + 16 * i - 1];
            acc[0][i] = fmaf(wa.x, xa, acc[0][i]);
            acc[1][i] = fmaf(wa.y, xa, acc[1][i]);
            acc[2][i] = fmaf(wa.z, xa, acc[2][i]);
            acc[3][i] = fmaf(wa.w, xa, acc[3][i]);
            acc[0][i] = fmaf(wb.x, xb, acc[0][i]);
            acc[1][i] = fmaf(wb.y, xb, acc[1][i]);
            acc[2][i] = fmaf(wb.z, xb, acc[2][i]);
            acc[3][i] = fmaf(wb.w, xb, acc[3][i]);
        }
    }
#pragma unroll
    for (int r = 0; r < 4; r++) {
        int oc = ocg * 4 + r;
        float bv = bias[oc];
#pragma unroll
        for (int i = 0; i < 4; i++)
            out[((size_t)(n * 32 + oc)) * 2048 + p0 + lane + 32 * i] =
                fmaxf(acc[r][i] + bv, 0.f);
    }
}

// ---------------------------------------------------------------------------
// ConvTranspose1d 32->64, K=4, S=2, P=1, bias. Tile 128 out. grid (32,16)
// ---------------------------------------------------------------------------
__global__ void __launch_bounds__(256) k_dect2(
    const float* __restrict__ x, const float* __restrict__ w,
    const float* __restrict__ bias, float* __restrict__ out)
{
    extern __shared__ float sm[];
    float* xs = sm;             // [32][66]
    float* ws = sm + 32 * 66;   // [32][4][64]
    const int n = blockIdx.y;
    const int p0 = blockIdx.x * 128;
    const int t0in = (p0 >> 1) - 1;
    const int tid = threadIdx.x, lane = tid & 31, ocg = tid >> 5;

    for (int idx = tid; idx < 32 * 66; idx += 256) {
        int c = idx / 66, j = idx - c * 66;
        int g = t0in + j;
        float v = 0.f;
        if (g >= 0 && g < 2048) v = x[((size_t)(n * 32 + c)) * 2048 + g];
        xs[idx] = v;
    }
    for (int idx = tid; idx < 32 * 4 * 64; idx += 256) {
        int o = idx & 63, ck = idx >> 6;
        int k = ck & 3, c = ck >> 2;
        ws[idx] = w[((size_t)c * 64 + o) * 4 + k];
    }
    __syncthreads();

    const int par = lane & 1;
    const int ka = 1 - par, kb = ka + 2;
    const int ja0 = ((lane + 1 - ka) >> 1) + 1;

    float acc[8][4];
#pragma unroll
    for (int r = 0; r < 8; r++)
#pragma unroll
        for (int i = 0; i < 4; i++) acc[r][i] = 0.f;

#pragma unroll 4
    for (int c = 0; c < 32; c++) {
        const float* xr = xs + c * 66;
        const float4* wr = (const float4*)(ws + c * 256);
        float4 wa0 = wr[ka * 16 + ocg * 2];
        float4 wa1 = wr[ka * 16 + ocg * 2 + 1];
        float4 wb0 = wr[kb * 16 + ocg * 2];
        float4 wb1 = wr[kb * 16 + ocg * 2 + 1];
#pragma unroll
        for (int i = 0; i < 4; i++) {
            float xa = xr[ja0 + 16 * i];
            float xb = xr[ja0 + 16 * i - 1];
            acc[0][i] = fmaf(wa0.x, xa, acc[0][i]);
            acc[1][i] = fmaf(wa0.y, xa, acc[1][i]);
            acc[2][i] = fmaf(wa0.z, xa, acc[2][i]);
            acc[3][i] = fmaf(wa0.w, xa, acc[3][i]);
            acc[4][i] = fmaf(wa1.x, xa, acc[4][i]);
            acc[5][i] = fmaf(wa1.y, xa, acc[5][i]);
            acc[6][i] = fmaf(wa1.z, xa, acc[6][i]);
            acc[7][i] = fmaf(wa1.w, xa, acc[7][i]);
            acc[0][i] = fmaf(wb0.x, xb, acc[0][i]);
            acc[1][i] = fmaf(wb0.y, xb, acc[1][i]);
            acc[2][i] = fmaf(wb0.z, xb, acc[2][i]);
            acc[3][i] = fmaf(wb0.w, xb, acc[3][i]);
            acc[4][i] = fmaf(wb1.x, xb, acc[4][i]);
            acc[5][i] = fmaf(wb1.y, xb, acc[5][i]);
            acc[6][i] = fmaf(wb1.z, xb, acc[6][i]);
            acc[7][i] = fmaf(wb1.w, xb, acc[7][i]);
        }
    }
#pragma unroll
    for (int r = 0; r < 8; r++) {
        int oc = ocg * 8 + r;
        float bv = bias[oc];
#pragma unroll
        for (int i = 0; i < 4; i++)
            out[((size_t)(n * 64 + oc)) * 4096 + p0 + lane + 32 * i] =
                acc[r][i] + bv;
    }
}

// ---------------------------------------------------------------------------
// Host orchestration
// ---------------------------------------------------------------------------
static const int SM_CONV1 = (32 * 130 + 32 * 4 * 32) * 4;                  // 33024
static const int SM_CONV2 = (32 * 130 + 32 * 4 * 64) * 4;                  // 49408
static const int SM_C3    = (64 * 66 + 64 * 3 * 64) * 4;                   // 66048
static const int SM_C1    = (64 * 64 + 64 * 64) * 4;                       // 32768
static const int SM_RES   = (64 * 66 + 64 * 3 * 32 + 32 * 64 + 32 * 64) * 4; // 57856
static const int SM_VQ    = (512 * 68 + 512) * 4 + 512 * 8 + 64 * 4;       // 145664
static const int SM_DT1   = (64 * 66 + 64 * 4 * 32) * 4;                   // 49664
static const int SM_DT2   = (32 * 66 + 32 * 4 * 64) * 4;                   // 41216

extern "C" void kernel_launch(void* const* d_in, const int* in_sizes, int n_in,
                              void* d_out, int out_size)
{
    (void)in_sizes; (void)n_in; (void)out_size;
    const float* x      = (const float*)d_in[0];
    const float* enc_w1 = (const float*)d_in[1];
    const float* enc_b1 = (const float*)d_in[2];
    const float* enc_w2 = (const float*)d_in[3];
    const float* enc_b2 = (const float*)d_in[4];
    const float* enc_w3 = (const float*)d_in[5];
    const float* enc_b3 = (const float*)d_in[6];
    const float* r0w1   = (const float*)d_in[7];
    const float* r0w2   = (const float*)d_in[8];
    const float* r1w1   = (const float*)d_in[9];
    const float* r1w2   = (const float*)d_in[10];
    const float* pvq_w  = (const float*)d_in[11];
    const float* pvq_b  = (const float*)d_in[12];
    const float* emb    = (const float*)d_in[13];
    const float* dw1    = (const float*)d_in[14];
    const float* db1    = (const float*)d_in[15];
    const float* dr0w1  = (const float*)d_in[16];
    const float* dr0w2  = (const float*)d_in[17];
    const float* dr1w1  = (const float*)d_in[18];
    const float* dr1w2  = (const float*)d_in[19];
    const float* dt1w   = (const float*)d_in[20];
    const float* dt1b   = (const float*)d_in[21];
    const float* dt2w   = (const float*)d_in[22];
    const float* dt2b   = (const float*)d_in[23];
    float* out = (float*)d_out;

    float *h1, *A, *Bb, *t1;
    cudaGetSymbolAddress((void**)&h1, g_h1);
    cudaGetSymbolAddress((void**)&A, g_bufA);
    cudaGetSymbolAddress((void**)&Bb, g_bufB);
    cudaGetSymbolAddress((void**)&t1, g_t1);

    cudaFuncSetAttribute(k_conv1, cudaFuncAttributeMaxDynamicSharedMemorySize, SM_CONV1);
    cudaFuncSetAttribute(k_conv2, cudaFuncAttributeMaxDynamicSharedMemorySize, SM_CONV2);
    cudaFuncSetAttribute(k_conv64<3, false>, cudaFuncAttributeMaxDynamicSharedMemorySize, SM_C3);
    cudaFuncSetAttribute(k_conv64<1, false>, cudaFuncAttributeMaxDynamicSharedMemorySize, SM_C1);
    cudaFuncSetAttribute(k_resblock<false>, cudaFuncAttributeMaxDynamicSharedMemorySize, SM_RES);
    cudaFuncSetAttribute(k_resblock<true>, cudaFuncAttributeMaxDynamicSharedMemorySize, SM_RES);
    cudaFuncSetAttribute(k_vq, cudaFuncAttributeMaxDynamicSharedMemorySize, SM_VQ);
    cudaFuncSetAttribute(k_dect1, cudaFuncAttributeMaxDynamicSharedMemorySize, SM_DT1);
    cudaFuncSetAttribute(k_dect2, cudaFuncAttributeMaxDynamicSharedMemorySize, SM_DT2);

    // Encoder
    k_conv1<<<dim3(32, 16), 256, SM_CONV1>>>(x, enc_w1, enc_b1, h1);
    k_conv2<<<dim3(16, 16), 256, SM_CONV2>>>(h1, enc_w2, enc_b2, A);
    k_conv64<3, false><<<dim3(16, 16), 256, SM_C3>>>(A, enc_w3, enc_b3, Bb);
    k_resblock<false><<<dim3(16, 16), 256, SM_RES>>>(Bb, r0w1, r0w2, A);
    k_resblock<true><<<dim3(16, 16), 256, SM_RES>>>(A, r1w1, r1w2, Bb);
    // pre-VQ 1x1 -> z
    k_conv64<1, false><<<dim3(16, 16), 256, SM_C1>>>(Bb, pvq_w, pvq_b, A);
    // VQ -> q
    k_vq<<<256, 512, SM_VQ>>>(A, emb, Bb);
    // Decoder
    k_conv64<3, false><<<dim3(16, 16), 256, SM_C3>>>(Bb, dw1, db1, A);
    k_resblock<false><<<dim3(16, 16), 256, SM_RES>>>(A, dr0w1, dr0w2, Bb);
    k_resblock<true><<<dim3(16, 16), 256, SM_RES>>>(Bb, dr1w1, dr1w2, A);
    k_dect1<<<dim3(16, 16), 256, SM_DT1>>>(A, dt1w, dt1b, t1);
    k_dect2<<<dim3(32, 16), 256, SM_DT2>>>(t1, dt2w, dt2b, out);
}